// round 2
// baseline (speedup 1.0000x reference)
#include <cuda_runtime.h>

#define Tt 4
#define Bb 16
#define CIN 3
#define HIMG 64
#define WIMG 64
#define NN 6
#define COUT 128
#define HP 32
#define WP 32

// ---------------- device scratch (static, no allocation) ----------------
__device__ float g_out0[Bb*COUT*HP*WP];          // pooled node-0 output (8.4 MB)
__device__ float g_v0[Bb*COUT*HIMG*WIMG];        // PLIF state node 0 (33.5 MB)
__device__ float g_vnodes[5*Bb*COUT*HP*WP];      // PLIF states nodes 1..5 (42 MB)
__device__ float g_traces[Bb*NN*COUT];
__device__ float g_feat0[Bb*COUT];
__device__ float g_accum[NN*Bb*COUT];            // slot0 = mean0 sums, slots1..5 = spike sums
__device__ float g_cvec[Bb*NN];                  // (op^2)[:, :, 0]

// ---------------- kernel 1: conv0 + bn + plif0 + spike + pool + partial mean ----------------
__global__ __launch_bounds__(256) void conv0_kernel(
    const float* __restrict__ x, const float* __restrict__ w,
    const float* __restrict__ bg, const float* __restrict__ bbias,
    const float* __restrict__ bm, const float* __restrict__ bv,
    const float* __restrict__ plifw, const float* __restrict__ outw,
    float* __restrict__ v0, float* __restrict__ out0,
    float* __restrict__ outT, float* __restrict__ mean0)
{
    int q = blockIdx.x, co = blockIdx.y, b = blockIdx.z;
    int tid = threadIdx.x;
    int ph = ((q >> 1) << 4) + (tid >> 4);
    int pw = ((q & 1) << 4) + (tid & 15);

    float wr[27];
    const float* wp = w + co * 27;
    #pragma unroll
    for (int i = 0; i < 27; i++) wr[i] = wp[i];

    float scale = bg[co] * rsqrtf(bv[co] + 1e-5f);
    float mm = bm[co], bc = bbias[co];
    float sig = 1.f / (1.f + expf(-plifw[0]));

    const float* xb = x + (size_t)b * (CIN*HIMG*WIMG);
    float* vp = v0 + ((size_t)b*COUT + co) * (HIMG*WIMG);

    float s4 = 0.f;
    #pragma unroll
    for (int dy = 0; dy < 2; dy++)
    #pragma unroll
    for (int dx = 0; dx < 2; dx++) {
        int y = ph*2 + dy, xx = pw*2 + dx;
        float acc = 0.f;
        #pragma unroll
        for (int ci = 0; ci < 3; ci++)
        #pragma unroll
        for (int r = 0; r < 3; r++) {
            int yy = y + r - 1;
            if (yy < 0 || yy >= 64) continue;
            #pragma unroll
            for (int s = 0; s < 3; s++) {
                int xs = xx + s - 1;
                if (xs < 0 || xs >= 64) continue;
                acc = fmaf(wr[ci*9+r*3+s], __ldg(&xb[ci*4096 + yy*64 + xs]), acc);
            }
        }
        float xbn = (acc - mm) * scale + bc;
        int idx = y*64 + xx;
        float vold = vp[idx];
        float v = vold + (xbn - vold) * sig;
        float sp = (v >= 1.f) ? 1.f : 0.f;
        vp[idx] = v * (1.f - sp);
        s4 += sp;
    }
    float pooled = s4 * 0.25f;
    int pidx = (b*COUT + co)*1024 + ph*32 + pw;
    out0[pidx] = pooled;
    float ws0 = 1.f / (1.f + expf(-outw[0]));
    outT[pidx] = ws0 * pooled;

    // block-reduce pooled -> sum for out0.mean((2,3))
    float p = pooled;
    #pragma unroll
    for (int off = 16; off; off >>= 1) p += __shfl_down_sync(0xffffffffu, p, off);
    __shared__ float red[8];
    int lane = tid & 31, wrp = tid >> 5;
    if (lane == 0) red[wrp] = p;
    __syncthreads();
    if (tid == 0) {
        float s = 0.f;
        #pragma unroll
        for (int i = 0; i < 8; i++) s += red[i];
        atomicAdd(&mean0[b*COUT + co], s);
    }
}

// ---------------- kernel 2: feat0 + trace row0 + GAT + softmax + prune + diffusion + c ----------------
__global__ __launch_bounds__(128) void graph_kernel(
    const float* __restrict__ accum, const float* __restrict__ ftw,
    const float* __restrict__ ftb, const float* __restrict__ gatW,
    const float* __restrict__ gata, float* __restrict__ traces,
    float* __restrict__ feat0buf, float* __restrict__ cvec)
{
    int b = blockIdx.x;
    int c = threadIdx.x;
    __shared__ float sm0[128];
    __shared__ float trSh[6][128];
    __shared__ float tile[32*129];
    __shared__ float e1s[6][4], e2s[6][4];
    __shared__ float Ss[6][6], Spm[6][6], adjm[6][6], opm[6][6], dism[6];

    sm0[c] = accum[b*128 + c] * (1.f/1024.f);
    #pragma unroll
    for (int n = 1; n < 6; n++) trSh[n][c] = traces[(b*6 + n)*128 + c];
    __syncthreads();

    // feat0[c] = relu(sum_k mean0[k] * ftw[c,k] + ftb[c])  (coalesced via transposed smem tiles)
    float acc = ftb[c];
    for (int k0 = 0; k0 < 128; k0 += 32) {
        for (int idx = c; idx < 128*32; idx += 128) {
            int cr = idx >> 5, kk = idx & 31;
            tile[kk*129 + cr] = ftw[cr*128 + k0 + kk];
        }
        __syncthreads();
        #pragma unroll
        for (int kk = 0; kk < 32; kk++)
            acc = fmaf(sm0[k0+kk], tile[kk*129 + c], acc);
        __syncthreads();
    }
    float f0 = fmaxf(acc, 0.f);
    feat0buf[b*128 + c] = f0;
    float t0 = 0.6f * traces[(b*6)*128 + c] + 0.4f * f0;
    traces[(b*6)*128 + c] = t0;
    trSh[0][c] = t0;
    __syncthreads();

    // hp[n][c] = sum_k traces[n,k] * gatW[c,k]
    float hacc[6] = {0.f,0.f,0.f,0.f,0.f,0.f};
    for (int k0 = 0; k0 < 128; k0 += 32) {
        for (int idx = c; idx < 128*32; idx += 128) {
            int cr = idx >> 5, kk = idx & 31;
            tile[kk*129 + cr] = gatW[cr*128 + k0 + kk];
        }
        __syncthreads();
        #pragma unroll
        for (int kk = 0; kk < 32; kk++) {
            float wv = tile[kk*129 + c];
            #pragma unroll
            for (int n = 0; n < 6; n++)
                hacc[n] = fmaf(trSh[n][k0+kk], wv, hacc[n]);
        }
        __syncthreads();
    }

    // e1/e2 per (n, head): warp = head, lane = dim
    int h = c >> 5, d = c & 31;
    float a1 = gata[h*64 + d], a2 = gata[h*64 + 32 + d];
    #pragma unroll
    for (int n = 0; n < 6; n++) {
        float p1 = hacc[n] * a1;
        float p2 = hacc[n] * a2;
        #pragma unroll
        for (int off = 16; off; off >>= 1) {
            p1 += __shfl_xor_sync(0xffffffffu, p1, off);
            p2 += __shfl_xor_sync(0xffffffffu, p2, off);
        }
        if (d == 0) { e1s[n][h] = p1; e2s[n][h] = p2; }
    }
    __syncthreads();

    if (c < 36) {
        int i = c / 6, j = c % 6;
        float s = 0.f;
        #pragma unroll
        for (int hh = 0; hh < 4; hh++) {
            float eij = e1s[i][hh] + e2s[j][hh]; eij = eij > 0.f ? eij : 0.2f * eij;
            float eji = e1s[j][hh] + e2s[i][hh]; eji = eji > 0.f ? eji : 0.2f * eji;
            s += 0.5f * (eij + eji);
        }
        Ss[i][j] = (s * 0.25f) * 100.f;   // mean over 4 heads, /0.01 temperature
    }
    __syncthreads();
    if (c < 6) {
        // stable softmax row c, then prune top-3
        float mx = -1e30f;
        for (int j = 0; j < 6; j++) mx = fmaxf(mx, Ss[c][j]);
        float ex[6]; float sum = 0.f;
        for (int j = 0; j < 6; j++) { ex[j] = expf(Ss[c][j] - mx); sum += ex[j]; }
        float v[6];
        for (int j = 0; j < 6; j++) { v[j] = ex[j] / sum; Ss[c][j] = v[j]; }
        for (int a_ = 0; a_ < 3; a_++) {
            int mi = a_;
            for (int j = a_+1; j < 6; j++) if (v[j] > v[mi]) mi = j;
            float tv = v[a_]; v[a_] = v[mi]; v[mi] = tv;
        }
        float kth = v[2];
        for (int j = 0; j < 6; j++) Spm[c][j] = (Ss[c][j] >= kth) ? Ss[c][j] : 0.f;
    }
    __syncthreads();
    if (c < 36) { int i = c/6, j = c%6; adjm[i][j] = 0.5f*(Spm[i][j] + Spm[j][i]); }
    __syncthreads();
    if (c < 6) {
        float dsum = 0.f;
        for (int j = 0; j < 6; j++) dsum += adjm[c][j];
        dism[c] = 1.f / sqrtf(dsum + 1e-6f);
    }
    __syncthreads();
    if (c < 36) { int i = c/6, j = c%6; opm[i][j] = dism[i]*adjm[i][j]*dism[j]; }
    __syncthreads();
    if (c < 6) {
        float s = 0.f;
        for (int j = 0; j < 6; j++) s += opm[c][j] * opm[j][0];
        cvec[b*6 + c] = s;   // (op^2)[c,0]
    }
}

// ---------------- kernel 3: 5 node convs (on out0, scaled in epilogue) + bn + plif + spike ----------------
__global__ __launch_bounds__(256, 2) void node_conv_kernel(
    const float* __restrict__ out0, const float* __restrict__ wts,
    const float* __restrict__ bg, const float* __restrict__ bbias,
    const float* __restrict__ bm, const float* __restrict__ bv,
    const float* __restrict__ plifw, const float* __restrict__ outw,
    const float* __restrict__ cvec, float* __restrict__ vnodes,
    float* __restrict__ outT, float* __restrict__ spsum)
{
    int pt = blockIdx.x;           // pixel row-tile (8 rows)
    int ct = blockIdx.y;           // 0..9 -> (node, co half)
    int b  = blockIdx.z;
    int node = ct >> 1;
    int co_base = (ct & 1) * 64;
    int tid = threadIdx.x, tx = tid & 31, ty = tid >> 5;

    __shared__ float sIn[8*10*34];   // 8 ci x 10 rows x 34 cols (halo, zero-padded)
    __shared__ float sW[64*8*9];     // 64 co x 8 ci x 9

    float acc[8][8];
    #pragma unroll
    for (int j = 0; j < 8; j++)
        #pragma unroll
        for (int k = 0; k < 8; k++) acc[j][k] = 0.f;

    const float* inb = out0 + (size_t)b * COUT * 1024;
    int y0 = pt * 8;

    for (int cb = 0; cb < 128; cb += 8) {
        // stage input tile (with halo)
        for (int idx = tid; idx < 2720; idx += 256) {
            int ci = idx / 340; int rem = idx - ci*340;
            int rr = rem / 34;  int cc = rem - rr*34;
            int gy = y0 - 1 + rr, gx = cc - 1;
            float v = 0.f;
            if (gy >= 0 && gy < 32 && gx >= 0 && gx < 32)
                v = inb[(cb+ci)*1024 + gy*32 + gx];
            sIn[idx] = v;
        }
        // stage weights
        const float* wbase = wts + ((size_t)(node*128 + co_base)*128 + cb)*9;
        for (int idx = tid; idx < 4608; idx += 256) {
            int col = idx / 72; int rem = idx - col*72;
            sW[idx] = wbase[(size_t)col*1152 + rem];
        }
        __syncthreads();

        for (int ci = 0; ci < 8; ci++) {
            const float* sI  = sIn + ci*340;
            const float* sWc = sW + (ty*8)*72 + ci*9;
            #pragma unroll
            for (int r = 0; r < 3; r++) {
                #pragma unroll
                for (int s = 0; s < 3; s++) {
                    float wv[8];
                    #pragma unroll
                    for (int j = 0; j < 8; j++) wv[j] = sWc[j*72 + r*3 + s];
                    float iv[8];
                    #pragma unroll
                    for (int k = 0; k < 8; k++) iv[k] = sI[(k+r)*34 + tx + s];
                    #pragma unroll
                    for (int j = 0; j < 8; j++)
                        #pragma unroll
                        for (int k = 0; k < 8; k++)
                            acc[j][k] = fmaf(wv[j], iv[k], acc[j][k]);
                }
            }
        }
        __syncthreads();
    }

    // epilogue: scale by c, bn, plif, spike, output add, spike-count reduce
    float sig = 1.f / (1.f + expf(-plifw[node+1]));
    float ws  = 1.f / (1.f + expf(-outw[node+1]));
    float csc = cvec[b*6 + node + 1];

    #pragma unroll
    for (int j = 0; j < 8; j++) {
        int co = co_base + ty*8 + j;
        float scale = bg[node*128+co] * rsqrtf(bv[node*128+co] + 1e-5f);
        float mm = bm[node*128+co], bc = bbias[node*128+co];
        float* vp = vnodes + ((size_t)(node*16 + b)*128 + co)*1024;
        float* op = outT + ((size_t)b*128 + co)*1024;
        float fs = 0.f;
        #pragma unroll
        for (int k = 0; k < 8; k++) {
            int px = (y0+k)*32 + tx;
            float xbn = (acc[j][k]*csc - mm)*scale + bc;
            float vold = vp[px];
            float v = vold + (xbn - vold)*sig;
            float sp = (v >= 1.f) ? 1.f : 0.f;
            vp[px] = v*(1.f - sp);
            if (sp != 0.f) { atomicAdd(&op[px], ws); fs += 1.f; }
        }
        #pragma unroll
        for (int off = 16; off; off >>= 1) fs += __shfl_down_sync(0xffffffffu, fs, off);
        if (tx == 0 && fs != 0.f)
            atomicAdd(&spsum[(node+1)*2048 + b*128 + co], fs);
    }
}

// ---------------- kernel 4: node feats GEMM + trace update (all 6 rows) ----------------
__global__ __launch_bounds__(128) void feats_kernel(
    const float* __restrict__ accum, const float* __restrict__ feat0buf,
    const float* __restrict__ ftw, const float* __restrict__ ftb,
    float* __restrict__ traces)
{
    int n = blockIdx.x, b = blockIdx.y;
    int c = threadIdx.x;
    __shared__ float sm[128];
    __shared__ float tile[32*129];
    float f;
    if (n == 0) {
        f = feat0buf[b*128 + c];
    } else {
        sm[c] = accum[n*2048 + b*128 + c] * (1.f/1024.f);
        __syncthreads();
        float acc = ftb[c];
        for (int k0 = 0; k0 < 128; k0 += 32) {
            for (int idx = c; idx < 128*32; idx += 128) {
                int cr = idx >> 5, kk = idx & 31;
                tile[kk*129 + cr] = ftw[cr*128 + k0 + kk];
            }
            __syncthreads();
            #pragma unroll
            for (int kk = 0; kk < 32; kk++)
                acc = fmaf(sm[k0+kk], tile[kk*129 + c], acc);
            __syncthreads();
        }
        f = fmaxf(acc, 0.f);
    }
    int idx = (b*6 + n)*128 + c;
    traces[idx] = 0.6f * traces[idx] + 0.4f * f;
}

// ---------------- launcher ----------------
extern "C" void kernel_launch(void* const* d_in, const int* in_sizes, int n_in,
                              void* d_out, int out_size)
{
    const float* x      = (const float*)d_in[0];
    const float* conv0w = (const float*)d_in[1];
    const float* bn0g   = (const float*)d_in[2];
    const float* bn0b   = (const float*)d_in[3];
    const float* bn0m   = (const float*)d_in[4];
    const float* bn0v   = (const float*)d_in[5];
    const float* convsw = (const float*)d_in[6];
    const float* bnsg   = (const float*)d_in[7];
    const float* bnsb   = (const float*)d_in[8];
    const float* bnsm   = (const float*)d_in[9];
    const float* bnsv   = (const float*)d_in[10];
    const float* plifw  = (const float*)d_in[11];
    const float* ftw    = (const float*)d_in[12];
    const float* ftb    = (const float*)d_in[13];
    const float* gatW   = (const float*)d_in[14];
    const float* gata   = (const float*)d_in[15];
    const float* outw   = (const float*)d_in[16];
    float* out = (float*)d_out;

    float *p_out0, *p_v0, *p_vn, *p_tr, *p_f0, *p_ac, *p_cv;
    cudaGetSymbolAddress((void**)&p_out0, g_out0);
    cudaGetSymbolAddress((void**)&p_v0,   g_v0);
    cudaGetSymbolAddress((void**)&p_vn,   g_vnodes);
    cudaGetSymbolAddress((void**)&p_tr,   g_traces);
    cudaGetSymbolAddress((void**)&p_f0,   g_feat0);
    cudaGetSymbolAddress((void**)&p_ac,   g_accum);
    cudaGetSymbolAddress((void**)&p_cv,   g_cvec);

    // reset recurrent state every call (deterministic)
    cudaMemsetAsync(p_v0, 0, sizeof(g_v0));
    cudaMemsetAsync(p_vn, 0, sizeof(g_vnodes));
    cudaMemsetAsync(p_tr, 0, sizeof(g_traces));

    for (int t = 0; t < Tt; t++) {
        cudaMemsetAsync(p_ac, 0, sizeof(g_accum));
        const float* xt = x + (size_t)t * Bb * CIN * HIMG * WIMG;
        float* outT = out + (size_t)t * Bb * COUT * HP * WP;

        conv0_kernel<<<dim3(4,128,16), 256>>>(xt, conv0w, bn0g, bn0b, bn0m, bn0v,
                                              plifw, outw, p_v0, p_out0, outT, p_ac);
        graph_kernel<<<16, 128>>>(p_ac, ftw, ftb, gatW, gata, p_tr, p_f0, p_cv);
        node_conv_kernel<<<dim3(4,10,16), 256>>>(p_out0, convsw, bnsg, bnsb, bnsm, bnsv,
                                                 plifw, outw, p_cv, p_vn, outT, p_ac);
        feats_kernel<<<dim3(6,16), 128>>>(p_ac, p_f0, ftw, ftb, p_tr);
    }
}

// round 3
// speedup vs baseline: 1.7842x; 1.7842x over previous
#include <cuda_runtime.h>

#define Tt 4
#define Bb 16
#define CIN 3
#define HIMG 64
#define WIMG 64
#define NN 6
#define COUT 128
#define HP 32
#define WP 32

// ---------------- device scratch (static, no allocation) ----------------
__device__ float g_out0[Bb*COUT*HP*WP];          // pooled node-0 output
__device__ float g_v0[Bb*COUT*HIMG*WIMG];        // PLIF state node 0
__device__ float g_vnodes[5*Bb*COUT*HP*WP];      // PLIF states nodes 1..5
__device__ float g_traces[Bb*NN*COUT];
__device__ float g_feat0[Bb*COUT];
__device__ float g_accum[NN*Bb*COUT];            // slot0 = mean0 sums, slots1..5 = spike sums
__device__ float g_cvec[Bb*NN];                  // (op^2)[:, :, 0]

// ---------------- kernel 1: conv0 + bn + plif0 + spike + pool + partial mean ----------------
__global__ __launch_bounds__(256) void conv0_kernel(
    const float* __restrict__ x, const float* __restrict__ w,
    const float* __restrict__ bg, const float* __restrict__ bbias,
    const float* __restrict__ bm, const float* __restrict__ bv,
    const float* __restrict__ plifw, const float* __restrict__ outw,
    float* __restrict__ v0, float* __restrict__ out0,
    float* __restrict__ outT, float* __restrict__ mean0)
{
    int q = blockIdx.x, co = blockIdx.y, b = blockIdx.z;
    int tid = threadIdx.x;
    int ph = ((q >> 1) << 4) + (tid >> 4);
    int pw = ((q & 1) << 4) + (tid & 15);

    float wr[27];
    const float* wp = w + co * 27;
    #pragma unroll
    for (int i = 0; i < 27; i++) wr[i] = wp[i];

    float scale = bg[co] * rsqrtf(bv[co] + 1e-5f);
    float mm = bm[co], bc = bbias[co];
    float sig = 1.f / (1.f + expf(-plifw[0]));

    const float* xb = x + (size_t)b * (CIN*HIMG*WIMG);
    float* vp = v0 + ((size_t)b*COUT + co) * (HIMG*WIMG);

    float s4 = 0.f;
    #pragma unroll
    for (int dy = 0; dy < 2; dy++)
    #pragma unroll
    for (int dx = 0; dx < 2; dx++) {
        int y = ph*2 + dy, xx = pw*2 + dx;
        float acc = 0.f;
        #pragma unroll
        for (int ci = 0; ci < 3; ci++)
        #pragma unroll
        for (int r = 0; r < 3; r++) {
            int yy = y + r - 1;
            if (yy < 0 || yy >= 64) continue;
            #pragma unroll
            for (int s = 0; s < 3; s++) {
                int xs = xx + s - 1;
                if (xs < 0 || xs >= 64) continue;
                acc = fmaf(wr[ci*9+r*3+s], __ldg(&xb[ci*4096 + yy*64 + xs]), acc);
            }
        }
        float xbn = (acc - mm) * scale + bc;
        int idx = y*64 + xx;
        float vold = vp[idx];
        float v = vold + (xbn - vold) * sig;
        float sp = (v >= 1.f) ? 1.f : 0.f;
        vp[idx] = v * (1.f - sp);
        s4 += sp;
    }
    float pooled = s4 * 0.25f;
    int pidx = (b*COUT + co)*1024 + ph*32 + pw;
    out0[pidx] = pooled;
    float ws0 = 1.f / (1.f + expf(-outw[0]));
    outT[pidx] = ws0 * pooled;

    float p = pooled;
    #pragma unroll
    for (int off = 16; off; off >>= 1) p += __shfl_down_sync(0xffffffffu, p, off);
    __shared__ float red[8];
    int lane = tid & 31, wrp = tid >> 5;
    if (lane == 0) red[wrp] = p;
    __syncthreads();
    if (tid == 0) {
        float s = 0.f;
        #pragma unroll
        for (int i = 0; i < 8; i++) s += red[i];
        atomicAdd(&mean0[b*COUT + co], s);
    }
}

// ---------------- kernel 2: feat0 + trace row0 + GAT + softmax + prune + diffusion + c ----------------
__global__ __launch_bounds__(128) void graph_kernel(
    const float* __restrict__ accum, const float* __restrict__ ftw,
    const float* __restrict__ ftb, const float* __restrict__ gatW,
    const float* __restrict__ gata, float* __restrict__ traces,
    float* __restrict__ feat0buf, float* __restrict__ cvec)
{
    int b = blockIdx.x;
    int c = threadIdx.x;
    __shared__ float sm0[128];
    __shared__ float trSh[6][128];
    __shared__ float tile[32*129];
    __shared__ float e1s[6][4], e2s[6][4];
    __shared__ float Ss[6][6], Spm[6][6], adjm[6][6], opm[6][6], dism[6];

    sm0[c] = accum[b*128 + c] * (1.f/1024.f);
    #pragma unroll
    for (int n = 1; n < 6; n++) trSh[n][c] = traces[(b*6 + n)*128 + c];
    __syncthreads();

    float acc = ftb[c];
    for (int k0 = 0; k0 < 128; k0 += 32) {
        for (int idx = c; idx < 128*32; idx += 128) {
            int cr = idx >> 5, kk = idx & 31;
            tile[kk*129 + cr] = ftw[cr*128 + k0 + kk];
        }
        __syncthreads();
        #pragma unroll
        for (int kk = 0; kk < 32; kk++)
            acc = fmaf(sm0[k0+kk], tile[kk*129 + c], acc);
        __syncthreads();
    }
    float f0 = fmaxf(acc, 0.f);
    feat0buf[b*128 + c] = f0;
    float t0 = 0.6f * traces[(b*6)*128 + c] + 0.4f * f0;
    traces[(b*6)*128 + c] = t0;
    trSh[0][c] = t0;
    __syncthreads();

    float hacc[6] = {0.f,0.f,0.f,0.f,0.f,0.f};
    for (int k0 = 0; k0 < 128; k0 += 32) {
        for (int idx = c; idx < 128*32; idx += 128) {
            int cr = idx >> 5, kk = idx & 31;
            tile[kk*129 + cr] = gatW[cr*128 + k0 + kk];
        }
        __syncthreads();
        #pragma unroll
        for (int kk = 0; kk < 32; kk++) {
            float wv = tile[kk*129 + c];
            #pragma unroll
            for (int n = 0; n < 6; n++)
                hacc[n] = fmaf(trSh[n][k0+kk], wv, hacc[n]);
        }
        __syncthreads();
    }

    int h = c >> 5, d = c & 31;
    float a1 = gata[h*64 + d], a2 = gata[h*64 + 32 + d];
    #pragma unroll
    for (int n = 0; n < 6; n++) {
        float p1 = hacc[n] * a1;
        float p2 = hacc[n] * a2;
        #pragma unroll
        for (int off = 16; off; off >>= 1) {
            p1 += __shfl_xor_sync(0xffffffffu, p1, off);
            p2 += __shfl_xor_sync(0xffffffffu, p2, off);
        }
        if (d == 0) { e1s[n][h] = p1; e2s[n][h] = p2; }
    }
    __syncthreads();

    if (c < 36) {
        int i = c / 6, j = c % 6;
        float s = 0.f;
        #pragma unroll
        for (int hh = 0; hh < 4; hh++) {
            float eij = e1s[i][hh] + e2s[j][hh]; eij = eij > 0.f ? eij : 0.2f * eij;
            float eji = e1s[j][hh] + e2s[i][hh]; eji = eji > 0.f ? eji : 0.2f * eji;
            s += 0.5f * (eij + eji);
        }
        Ss[i][j] = (s * 0.25f) * 100.f;
    }
    __syncthreads();
    if (c < 6) {
        float mx = -1e30f;
        for (int j = 0; j < 6; j++) mx = fmaxf(mx, Ss[c][j]);
        float ex[6]; float sum = 0.f;
        for (int j = 0; j < 6; j++) { ex[j] = expf(Ss[c][j] - mx); sum += ex[j]; }
        float v[6];
        for (int j = 0; j < 6; j++) { v[j] = ex[j] / sum; Ss[c][j] = v[j]; }
        for (int a_ = 0; a_ < 3; a_++) {
            int mi = a_;
            for (int j = a_+1; j < 6; j++) if (v[j] > v[mi]) mi = j;
            float tv = v[a_]; v[a_] = v[mi]; v[mi] = tv;
        }
        float kth = v[2];
        for (int j = 0; j < 6; j++) Spm[c][j] = (Ss[c][j] >= kth) ? Ss[c][j] : 0.f;
    }
    __syncthreads();
    if (c < 36) { int i = c/6, j = c%6; adjm[i][j] = 0.5f*(Spm[i][j] + Spm[j][i]); }
    __syncthreads();
    if (c < 6) {
        float dsum = 0.f;
        for (int j = 0; j < 6; j++) dsum += adjm[c][j];
        dism[c] = 1.f / sqrtf(dsum + 1e-6f);
    }
    __syncthreads();
    if (c < 36) { int i = c/6, j = c%6; opm[i][j] = dism[i]*adjm[i][j]*dism[j]; }
    __syncthreads();
    if (c < 6) {
        float s = 0.f;
        for (int j = 0; j < 6; j++) s += opm[c][j] * opm[j][0];
        cvec[b*6 + c] = s;
    }
}

// ---------------- kernel 3: 5 node convs with packed f32x2 FMA ----------------
// sW layout: [32 co-pairs][8 ci][9 taps][2] -> weight pairs (co even, co odd) adjacent.
__global__ __launch_bounds__(256, 2) void node_conv_kernel(
    const float* __restrict__ out0, const float* __restrict__ wts,
    const float* __restrict__ bg, const float* __restrict__ bbias,
    const float* __restrict__ bm, const float* __restrict__ bv,
    const float* __restrict__ plifw, const float* __restrict__ outw,
    const float* __restrict__ cvec, float* __restrict__ vnodes,
    float* __restrict__ outT, float* __restrict__ spsum)
{
    int pt = blockIdx.x;           // pixel row-tile (8 rows)
    int ct = blockIdx.y;           // 0..9 -> (node, co half)
    int b  = blockIdx.z;
    int node = ct >> 1;
    int co_base = (ct & 1) * 64;
    int tid = threadIdx.x, tx = tid & 31, ty = tid >> 5;

    __shared__ float sIn[8*10*34];                 // 8 ci x 10 rows x 34 cols (halo)
    __shared__ __align__(8) float sW[64*8*9];      // 32 pairs x 8 ci x 9 taps x 2

    // acc pairs: [co-pair 0..3][row 0..7], lo half = even co, hi half = odd co
    unsigned long long acc[4][8];
    #pragma unroll
    for (int jp = 0; jp < 4; jp++)
        #pragma unroll
        for (int k = 0; k < 8; k++) acc[jp][k] = 0ull;

    const float* inb = out0 + (size_t)b * COUT * 1024;
    int y0 = pt * 8;

    for (int cb = 0; cb < 128; cb += 8) {
        // stage input tile (with halo)
        for (int idx = tid; idx < 2720; idx += 256) {
            int ci = idx / 340; int rem = idx - ci*340;
            int rr = rem / 34;  int cc = rem - rr*34;
            int gy = y0 - 1 + rr, gx = cc - 1;
            float v = 0.f;
            if (gy >= 0 && gy < 32 && gx >= 0 && gx < 32)
                v = inb[(cb+ci)*1024 + gy*32 + gx];
            sIn[idx] = v;
        }
        // stage weights into pair-major layout
        const float* wbase = wts + ((size_t)(node*128 + co_base)*128 + cb)*9;
        for (int idx = tid; idx < 4608; idx += 256) {
            int col = idx / 72; int rem = idx - col*72;   // col = co (0..63), rem = ci*9+t
            int ci = rem / 9, t = rem - ci*9;
            int cp = col >> 1, hh = col & 1;
            sW[(((cp*8 + ci)*9 + t) << 1) + hh] = wbase[(size_t)col*1152 + rem];
        }
        __syncthreads();

        const unsigned long long* sW64 = (const unsigned long long*)sW;
        for (int ci = 0; ci < 8; ci++) {
            const float* sI = sIn + ci*340;
            #pragma unroll
            for (int r = 0; r < 3; r++) {
                #pragma unroll
                for (int s = 0; s < 3; s++) {
                    int tap = r*3 + s;
                    unsigned long long wp[4];
                    #pragma unroll
                    for (int jp = 0; jp < 4; jp++)
                        wp[jp] = sW64[((ty*4 + jp)*8 + ci)*9 + tap];
                    #pragma unroll
                    for (int k = 0; k < 8; k++) {
                        unsigned int vi = __float_as_uint(sI[(k+r)*34 + tx + s]);
                        unsigned long long vv;
                        asm("mov.b64 %0, {%1, %1};" : "=l"(vv) : "r"(vi));
                        #pragma unroll
                        for (int jp = 0; jp < 4; jp++)
                            asm("fma.rn.f32x2 %0, %1, %2, %0;"
                                : "+l"(acc[jp][k]) : "l"(wp[jp]), "l"(vv));
                    }
                }
            }
        }
        __syncthreads();
    }

    // epilogue: unpack pairs, scale by c, bn, plif, spike, output add, spike-count
    float sig = 1.f / (1.f + expf(-plifw[node+1]));
    float ws  = 1.f / (1.f + expf(-outw[node+1]));
    float csc = cvec[b*6 + node + 1];

    #pragma unroll
    for (int jp = 0; jp < 4; jp++) {
        #pragma unroll
        for (int hh = 0; hh < 2; hh++) {
            int co = co_base + ty*8 + jp*2 + hh;
            float scale = bg[node*128+co] * rsqrtf(bv[node*128+co] + 1e-5f);
            float mm = bm[node*128+co], bc = bbias[node*128+co];
            float* vp = vnodes + ((size_t)(node*16 + b)*128 + co)*1024;
            float* op = outT + ((size_t)b*128 + co)*1024;
            float fs = 0.f;
            #pragma unroll
            for (int k = 0; k < 8; k++) {
                unsigned long long a = acc[jp][k];
                float av = __uint_as_float(hh ? (unsigned)(a >> 32) : (unsigned)(a & 0xffffffffull));
                int px = (y0+k)*32 + tx;
                float xbn = (av*csc - mm)*scale + bc;
                float vold = vp[px];
                float v = vold + (xbn - vold)*sig;
                float sp = (v >= 1.f) ? 1.f : 0.f;
                vp[px] = v*(1.f - sp);
                if (sp != 0.f) { atomicAdd(&op[px], ws); fs += 1.f; }
            }
            #pragma unroll
            for (int off = 16; off; off >>= 1) fs += __shfl_down_sync(0xffffffffu, fs, off);
            if (tx == 0 && fs != 0.f)
                atomicAdd(&spsum[(node+1)*2048 + b*128 + co], fs);
        }
    }
}

// ---------------- kernel 4: node feats GEMM + trace update (all 6 rows) ----------------
__global__ __launch_bounds__(128) void feats_kernel(
    const float* __restrict__ accum, const float* __restrict__ feat0buf,
    const float* __restrict__ ftw, const float* __restrict__ ftb,
    float* __restrict__ traces)
{
    int n = blockIdx.x, b = blockIdx.y;
    int c = threadIdx.x;
    __shared__ float sm[128];
    __shared__ float tile[32*129];
    float f;
    if (n == 0) {
        f = feat0buf[b*128 + c];
    } else {
        sm[c] = accum[n*2048 + b*128 + c] * (1.f/1024.f);
        __syncthreads();
        float acc = ftb[c];
        for (int k0 = 0; k0 < 128; k0 += 32) {
            for (int idx = c; idx < 128*32; idx += 128) {
                int cr = idx >> 5, kk = idx & 31;
                tile[kk*129 + cr] = ftw[cr*128 + k0 + kk];
            }
            __syncthreads();
            #pragma unroll
            for (int kk = 0; kk < 32; kk++)
                acc = fmaf(sm[k0+kk], tile[kk*129 + c], acc);
            __syncthreads();
        }
        f = fmaxf(acc, 0.f);
    }
    int idx = (b*6 + n)*128 + c;
    traces[idx] = 0.6f * traces[idx] + 0.4f * f;
}

// ---------------- launcher ----------------
extern "C" void kernel_launch(void* const* d_in, const int* in_sizes, int n_in,
                              void* d_out, int out_size)
{
    const float* x      = (const float*)d_in[0];
    const float* conv0w = (const float*)d_in[1];
    const float* bn0g   = (const float*)d_in[2];
    const float* bn0b   = (const float*)d_in[3];
    const float* bn0m   = (const float*)d_in[4];
    const float* bn0v   = (const float*)d_in[5];
    const float* convsw = (const float*)d_in[6];
    const float* bnsg   = (const float*)d_in[7];
    const float* bnsb   = (const float*)d_in[8];
    const float* bnsm   = (const float*)d_in[9];
    const float* bnsv   = (const float*)d_in[10];
    const float* plifw  = (const float*)d_in[11];
    const float* ftw    = (const float*)d_in[12];
    const float* ftb    = (const float*)d_in[13];
    const float* gatW   = (const float*)d_in[14];
    const float* gata   = (const float*)d_in[15];
    const float* outw   = (const float*)d_in[16];
    float* out = (float*)d_out;

    float *p_out0, *p_v0, *p_vn, *p_tr, *p_f0, *p_ac, *p_cv;
    cudaGetSymbolAddress((void**)&p_out0, g_out0);
    cudaGetSymbolAddress((void**)&p_v0,   g_v0);
    cudaGetSymbolAddress((void**)&p_vn,   g_vnodes);
    cudaGetSymbolAddress((void**)&p_tr,   g_traces);
    cudaGetSymbolAddress((void**)&p_f0,   g_feat0);
    cudaGetSymbolAddress((void**)&p_ac,   g_accum);
    cudaGetSymbolAddress((void**)&p_cv,   g_cvec);

    cudaMemsetAsync(p_v0, 0, sizeof(g_v0));
    cudaMemsetAsync(p_vn, 0, sizeof(g_vnodes));
    cudaMemsetAsync(p_tr, 0, sizeof(g_traces));

    for (int t = 0; t < Tt; t++) {
        cudaMemsetAsync(p_ac, 0, sizeof(g_accum));
        const float* xt = x + (size_t)t * Bb * CIN * HIMG * WIMG;
        float* outT = out + (size_t)t * Bb * COUT * HP * WP;

        conv0_kernel<<<dim3(4,128,16), 256>>>(xt, conv0w, bn0g, bn0b, bn0m, bn0v,
                                              plifw, outw, p_v0, p_out0, outT, p_ac);
        graph_kernel<<<16, 128>>>(p_ac, ftw, ftb, gatW, gata, p_tr, p_f0, p_cv);
        node_conv_kernel<<<dim3(4,10,16), 256>>>(p_out0, convsw, bnsg, bnsb, bnsm, bnsv,
                                                 plifw, outw, p_cv, p_vn, outT, p_ac);
        feats_kernel<<<dim3(6,16), 128>>>(p_ac, p_f0, ftw, ftb, p_tr);
    }
}